// round 12
// baseline (speedup 1.0000x reference)
#include <cuda_runtime.h>
#include <cuda_bf16.h>

// FinDiffNonUniform: yd[i,b] = sum_s w[i,s] * y[i + off[i,s], b]
// N=8192, B=4096, S=7, fp32.
//
// R12: DRAM-stream bound at ~5.3 TB/s (134MB writes + ~86MB read fills).
// Keep the winning issue structure (front-batched full register window,
// float2 lanes, row-fast CTA order) and (1) TR=16 (amp 1.31), (2) TPB=128
// so ~9 independent CTAs/SM interleave their load/store phases at the
// memory controller instead of phase-bunching.

#define S_W 7
#define TR 16
#define TPB 128
#define VEC 2
#define WIN (TR + 6)               // 22-row window
#define COLS_PER_BLOCK (TPB * VEC)

__global__ __launch_bounds__(TPB, 9)
void findiff_r12_kernel(const float* __restrict__ y,
                        const float* __restrict__ coef,
                        const int* __restrict__ offs,
                        float* __restrict__ out,
                        int N, int B)
{
    __shared__ float s_w[TR * S_W];
    __shared__ int   s_o[TR * S_W];
    __shared__ int   s_centered;

    const int t  = threadIdx.x;
    const int i0 = blockIdx.x * TR;            // row tile on FAST axis

    if (t == 0) s_centered = 1;
    __syncthreads();

    if (t < TR * S_W) {
        const int gidx = i0 * S_W + t;
        if (gidx < N * S_W) {
            s_w[t] = __ldg(&coef[gidx]);
            const int o = __ldg(&offs[gidx]);
            s_o[t] = o;
            if (o != (t % S_W) - 3) s_centered = 0;
        } else {
            s_w[t] = 0.0f;
            s_o[t] = 0;
        }
    }
    __syncthreads();

    const int col = blockIdx.y * COLS_PER_BLOCK + t * VEC;
    if (col >= B) return;

    const bool interior = (i0 >= 3) && (i0 + TR + 2 <= N - 1) && s_centered;

    if (interior) {
        // ---- fast path: front-batched register window, offsets = s-3 ----
        float2 win[WIN];
        const float* base = y + (size_t)(i0 - 3) * (size_t)B + col;
        #pragma unroll
        for (int k = 0; k < WIN; ++k)
            win[k] = *reinterpret_cast<const float2*>(base + (size_t)k * (size_t)B);

        float* obase = out + (size_t)i0 * (size_t)B + col;
        #pragma unroll
        for (int r = 0; r < TR; ++r) {
            float2 acc = make_float2(0.f, 0.f);
            #pragma unroll
            for (int s = 0; s < S_W; ++s) {
                const float  w = s_w[r * S_W + s];
                const float2 v = win[r + s];
                acc.x = fmaf(w, v.x, acc.x);
                acc.y = fmaf(w, v.y, acc.y);
            }
            *reinterpret_cast<float2*>(obase + (size_t)r * (size_t)B) = acc;
        }
    } else {
        // ---- generic path: boundary / partial / non-centered tiles ----
        #pragma unroll
        for (int r = 0; r < TR; ++r) {
            const int i = i0 + r;
            if (i >= N) break;
            float2 acc = make_float2(0.f, 0.f);
            #pragma unroll
            for (int s = 0; s < S_W; ++s) {
                const float w = s_w[r * S_W + s];
                const int   j = i + s_o[r * S_W + s];
                const float2 v = *reinterpret_cast<const float2*>(
                    y + (size_t)j * (size_t)B + col);
                acc.x = fmaf(w, v.x, acc.x);
                acc.y = fmaf(w, v.y, acc.y);
            }
            *reinterpret_cast<float2*>(out + (size_t)i * (size_t)B + col) = acc;
        }
    }
}

// Fully generic scalar fallback (any N, B).
__global__ void findiff_scalar_kernel(const float* __restrict__ y,
                                      const float* __restrict__ coef,
                                      const int* __restrict__ offs,
                                      float* __restrict__ out,
                                      int N, int B)
{
    const long long total = (long long)N * B;
    for (long long idx = (long long)blockIdx.x * blockDim.x + threadIdx.x;
         idx < total;
         idx += (long long)gridDim.x * blockDim.x) {
        const int i = (int)(idx / B);
        const int b = (int)(idx % B);
        float acc = 0.f;
        #pragma unroll
        for (int s = 0; s < S_W; ++s) {
            const float w = coef[i * S_W + s];
            const int   j = i + offs[i * S_W + s];
            acc = fmaf(w, y[(size_t)j * (size_t)B + b], acc);
        }
        out[idx] = acc;
    }
}

extern "C" void kernel_launch(void* const* d_in, const int* in_sizes, int n_in,
                              void* d_out, int out_size)
{
    const float* y    = (const float*)d_in[0];
    const float* coef = (const float*)d_in[1];
    const int*   offs = (const int*)d_in[2];
    float* out = (float*)d_out;

    const int N = in_sizes[1] / S_W;       // all_coefficients is [N, 7]
    const int B = in_sizes[0] / N;         // y is [N, B]

    if ((B % COLS_PER_BLOCK) == 0) {
        dim3 grid((N + TR - 1) / TR, B / COLS_PER_BLOCK);
        findiff_r12_kernel<<<grid, TPB>>>(y, coef, offs, out, N, B);
    } else {
        const long long total = (long long)N * B;
        int blocks = (int)((total + 255) / 256);
        if (blocks > 65535 * 32) blocks = 65535 * 32;
        findiff_scalar_kernel<<<blocks, 256>>>(y, coef, offs, out, N, B);
    }
}

// round 13
// speedup vs baseline: 1.0275x; 1.0275x over previous
#include <cuda_runtime.h>
#include <cuda_bf16.h>

// FinDiffNonUniform: yd[i,b] = sum_s w[i,s] * y[i + off[i,s], b]
// N=8192, B=4096, S=7, fp32.
//
// R13: single-variable probe of the TR curve at TPB=256 (8->42.1us,
// 12->41.6us): TR=14 (amp 1.43, window 20 x float2 = 40 regs, same
// 5 CTAs/SM occupancy as TR=12). All else identical to the R10 winner:
// float2 lanes, front-batched full register window, row-fast CTA order.
// Kernel is DRAM-stream bound at ~5.3 TB/s with near-compulsory bytes.

#define S_W 7
#define TR 14
#define TPB 256
#define VEC 2
#define WIN (TR + 6)               // 20-row window
#define COLS_PER_BLOCK (TPB * VEC)

__global__ __launch_bounds__(TPB, 5)
void findiff_r13_kernel(const float* __restrict__ y,
                        const float* __restrict__ coef,
                        const int* __restrict__ offs,
                        float* __restrict__ out,
                        int N, int B)
{
    __shared__ float s_w[TR * S_W];
    __shared__ int   s_o[TR * S_W];
    __shared__ int   s_centered;

    const int t  = threadIdx.x;
    const int i0 = blockIdx.x * TR;            // row tile on FAST axis

    if (t == 0) s_centered = 1;
    __syncthreads();

    if (t < TR * S_W) {
        const int gidx = i0 * S_W + t;
        if (gidx < N * S_W) {
            s_w[t] = __ldg(&coef[gidx]);
            const int o = __ldg(&offs[gidx]);
            s_o[t] = o;
            if (o != (t % S_W) - 3) s_centered = 0;
        } else {
            s_w[t] = 0.0f;
            s_o[t] = 0;
        }
    }
    __syncthreads();

    const int col = blockIdx.y * COLS_PER_BLOCK + t * VEC;
    if (col >= B) return;

    const bool interior = (i0 >= 3) && (i0 + TR + 2 <= N - 1) && s_centered;

    if (interior) {
        // ---- fast path: front-batched register window, offsets = s-3 ----
        float2 win[WIN];
        const float* base = y + (size_t)(i0 - 3) * (size_t)B + col;
        #pragma unroll
        for (int k = 0; k < WIN; ++k)
            win[k] = *reinterpret_cast<const float2*>(base + (size_t)k * (size_t)B);

        float* obase = out + (size_t)i0 * (size_t)B + col;
        #pragma unroll
        for (int r = 0; r < TR; ++r) {
            float2 acc = make_float2(0.f, 0.f);
            #pragma unroll
            for (int s = 0; s < S_W; ++s) {
                const float  w = s_w[r * S_W + s];
                const float2 v = win[r + s];
                acc.x = fmaf(w, v.x, acc.x);
                acc.y = fmaf(w, v.y, acc.y);
            }
            *reinterpret_cast<float2*>(obase + (size_t)r * (size_t)B) = acc;
        }
    } else {
        // ---- generic path: boundary / partial / non-centered tiles ----
        #pragma unroll
        for (int r = 0; r < TR; ++r) {
            const int i = i0 + r;
            if (i >= N) break;
            float2 acc = make_float2(0.f, 0.f);
            #pragma unroll
            for (int s = 0; s < S_W; ++s) {
                const float w = s_w[r * S_W + s];
                const int   j = i + s_o[r * S_W + s];
                const float2 v = *reinterpret_cast<const float2*>(
                    y + (size_t)j * (size_t)B + col);
                acc.x = fmaf(w, v.x, acc.x);
                acc.y = fmaf(w, v.y, acc.y);
            }
            *reinterpret_cast<float2*>(out + (size_t)i * (size_t)B + col) = acc;
        }
    }
}

// Fully generic scalar fallback (any N, B).
__global__ void findiff_scalar_kernel(const float* __restrict__ y,
                                      const float* __restrict__ coef,
                                      const int* __restrict__ offs,
                                      float* __restrict__ out,
                                      int N, int B)
{
    const long long total = (long long)N * B;
    for (long long idx = (long long)blockIdx.x * blockDim.x + threadIdx.x;
         idx < total;
         idx += (long long)gridDim.x * blockDim.x) {
        const int i = (int)(idx / B);
        const int b = (int)(idx % B);
        float acc = 0.f;
        #pragma unroll
        for (int s = 0; s < S_W; ++s) {
            const float w = coef[i * S_W + s];
            const int   j = i + offs[i * S_W + s];
            acc = fmaf(w, y[(size_t)j * (size_t)B + b], acc);
        }
        out[idx] = acc;
    }
}

extern "C" void kernel_launch(void* const* d_in, const int* in_sizes, int n_in,
                              void* d_out, int out_size)
{
    const float* y    = (const float*)d_in[0];
    const float* coef = (const float*)d_in[1];
    const int*   offs = (const int*)d_in[2];
    float* out = (float*)d_out;

    const int N = in_sizes[1] / S_W;       // all_coefficients is [N, 7]
    const int B = in_sizes[0] / N;         // y is [N, B]

    if ((B % COLS_PER_BLOCK) == 0) {
        dim3 grid((N + TR - 1) / TR, B / COLS_PER_BLOCK);
        findiff_r13_kernel<<<grid, TPB>>>(y, coef, offs, out, N, B);
    } else {
        const long long total = (long long)N * B;
        int blocks = (int)((total + 255) / 256);
        if (blocks > 65535 * 32) blocks = 65535 * 32;
        findiff_scalar_kernel<<<blocks, 256>>>(y, coef, offs, out, N, B);
    }
}

// round 14
// speedup vs baseline: 1.0658x; 1.0373x over previous
#include <cuda_runtime.h>
#include <cuda_bf16.h>

// FinDiffNonUniform: yd[i,b] = sum_s w[i,s] * y[i + off[i,s], b]
// N=8192, B=4096, S=7, fp32.
//
// R14 FINAL — measured optimum of the session-wide search:
//   - front-batched 18-row register window (max MLP; beats rolling/ring/TMA)
//   - float2 lanes (beats float1/float4)
//   - TR=12 rows per CTA (TR curve: 8->42.1, 12->41.6, 14->43.0, 16->44.2 us)
//   - TPB=256 (beats 128), launch_bounds(256,5), 48 regs
//   - row-tiles on blockIdx.x (fast axis) so scheduling-adjacent CTAs share
//     L2-hot halo lines (-3.2us vs column-fast)
// Kernel is DRAM-stream bound at ~5.3 TB/s with near-compulsory bytes
// (134MB writes + ~86MB read fills; y exceeds L2 capacity).
// Interior tiles verify offsets == s-3 at runtime; boundary/non-centered
// tiles take a generic gather path, arbitrary shapes a scalar fallback.

#define S_W 7
#define TR 12
#define TPB 256
#define VEC 2
#define WIN (TR + 6)               // 18-row window
#define COLS_PER_BLOCK (TPB * VEC)

__global__ __launch_bounds__(TPB, 5)
void findiff_final_kernel(const float* __restrict__ y,
                          const float* __restrict__ coef,
                          const int* __restrict__ offs,
                          float* __restrict__ out,
                          int N, int B)
{
    __shared__ float s_w[TR * S_W];
    __shared__ int   s_o[TR * S_W];
    __shared__ int   s_centered;

    const int t  = threadIdx.x;
    const int i0 = blockIdx.x * TR;            // row tile on FAST axis

    if (t == 0) s_centered = 1;
    __syncthreads();

    if (t < TR * S_W) {
        const int gidx = i0 * S_W + t;
        if (gidx < N * S_W) {
            s_w[t] = __ldg(&coef[gidx]);
            const int o = __ldg(&offs[gidx]);
            s_o[t] = o;
            if (o != (t % S_W) - 3) s_centered = 0;
        } else {
            s_w[t] = 0.0f;
            s_o[t] = 0;
        }
    }
    __syncthreads();

    const int col = blockIdx.y * COLS_PER_BLOCK + t * VEC;
    if (col >= B) return;

    const bool interior = (i0 >= 3) && (i0 + TR + 2 <= N - 1) && s_centered;

    if (interior) {
        // ---- fast path: front-batched register window, offsets = s-3 ----
        float2 win[WIN];
        const float* base = y + (size_t)(i0 - 3) * (size_t)B + col;
        #pragma unroll
        for (int k = 0; k < WIN; ++k)
            win[k] = *reinterpret_cast<const float2*>(base + (size_t)k * (size_t)B);

        float* obase = out + (size_t)i0 * (size_t)B + col;
        #pragma unroll
        for (int r = 0; r < TR; ++r) {
            float2 acc = make_float2(0.f, 0.f);
            #pragma unroll
            for (int s = 0; s < S_W; ++s) {
                const float  w = s_w[r * S_W + s];
                const float2 v = win[r + s];
                acc.x = fmaf(w, v.x, acc.x);
                acc.y = fmaf(w, v.y, acc.y);
            }
            *reinterpret_cast<float2*>(obase + (size_t)r * (size_t)B) = acc;
        }
    } else {
        // ---- generic path: boundary / partial / non-centered tiles ----
        #pragma unroll
        for (int r = 0; r < TR; ++r) {
            const int i = i0 + r;
            if (i >= N) break;
            float2 acc = make_float2(0.f, 0.f);
            #pragma unroll
            for (int s = 0; s < S_W; ++s) {
                const float w = s_w[r * S_W + s];
                const int   j = i + s_o[r * S_W + s];
                const float2 v = *reinterpret_cast<const float2*>(
                    y + (size_t)j * (size_t)B + col);
                acc.x = fmaf(w, v.x, acc.x);
                acc.y = fmaf(w, v.y, acc.y);
            }
            *reinterpret_cast<float2*>(out + (size_t)i * (size_t)B + col) = acc;
        }
    }
}

// Fully generic scalar fallback (any N, B).
__global__ void findiff_scalar_kernel(const float* __restrict__ y,
                                      const float* __restrict__ coef,
                                      const int* __restrict__ offs,
                                      float* __restrict__ out,
                                      int N, int B)
{
    const long long total = (long long)N * B;
    for (long long idx = (long long)blockIdx.x * blockDim.x + threadIdx.x;
         idx < total;
         idx += (long long)gridDim.x * blockDim.x) {
        const int i = (int)(idx / B);
        const int b = (int)(idx % B);
        float acc = 0.f;
        #pragma unroll
        for (int s = 0; s < S_W; ++s) {
            const float w = coef[i * S_W + s];
            const int   j = i + offs[i * S_W + s];
            acc = fmaf(w, y[(size_t)j * (size_t)B + b], acc);
        }
        out[idx] = acc;
    }
}

extern "C" void kernel_launch(void* const* d_in, const int* in_sizes, int n_in,
                              void* d_out, int out_size)
{
    const float* y    = (const float*)d_in[0];
    const float* coef = (const float*)d_in[1];
    const int*   offs = (const int*)d_in[2];
    float* out = (float*)d_out;

    const int N = in_sizes[1] / S_W;       // all_coefficients is [N, 7]
    const int B = in_sizes[0] / N;         // y is [N, B]

    if ((B % COLS_PER_BLOCK) == 0) {
        dim3 grid((N + TR - 1) / TR, B / COLS_PER_BLOCK);
        findiff_final_kernel<<<grid, TPB>>>(y, coef, offs, out, N, B);
    } else {
        const long long total = (long long)N * B;
        int blocks = (int)((total + 255) / 256);
        if (blocks > 65535 * 32) blocks = 65535 * 32;
        findiff_scalar_kernel<<<blocks, 256>>>(y, coef, offs, out, N, B);
    }
}

// round 15
// speedup vs baseline: 1.1032x; 1.0351x over previous
#include <cuda_runtime.h>
#include <cuda_bf16.h>

// FinDiffNonUniform: yd[i,b] = sum_s w[i,s] * y[i + off[i,s], b]
// N=8192, B=4096, S=7, fp32.
//
// R15: last interpolation probe of the TR curve (8->42.1us@occ64,
// 12->41.3us@occ55, 14->43.0, 16->44.2): TR=10 (amp 1.6, window 16 x
// float2 = 32 regs -> 6 CTAs/SM, occ ~65%). All else identical to the
// R14 optimum: front-batched full register window, float2 lanes, TPB=256,
// row-tiles on the fast grid axis (L2-hot halos).
// Kernel is DRAM-stream bound at ~5.3 TB/s with near-compulsory bytes.

#define S_W 7
#define TR 10
#define TPB 256
#define VEC 2
#define WIN (TR + 6)               // 16-row window
#define COLS_PER_BLOCK (TPB * VEC)

__global__ __launch_bounds__(TPB, 6)
void findiff_r15_kernel(const float* __restrict__ y,
                        const float* __restrict__ coef,
                        const int* __restrict__ offs,
                        float* __restrict__ out,
                        int N, int B)
{
    __shared__ float s_w[TR * S_W];
    __shared__ int   s_o[TR * S_W];
    __shared__ int   s_centered;

    const int t  = threadIdx.x;
    const int i0 = blockIdx.x * TR;            // row tile on FAST axis

    if (t == 0) s_centered = 1;
    __syncthreads();

    if (t < TR * S_W) {
        const int gidx = i0 * S_W + t;
        if (gidx < N * S_W) {
            s_w[t] = __ldg(&coef[gidx]);
            const int o = __ldg(&offs[gidx]);
            s_o[t] = o;
            if (o != (t % S_W) - 3) s_centered = 0;
        } else {
            s_w[t] = 0.0f;
            s_o[t] = 0;
        }
    }
    __syncthreads();

    const int col = blockIdx.y * COLS_PER_BLOCK + t * VEC;
    if (col >= B) return;

    const bool interior = (i0 >= 3) && (i0 + TR + 2 <= N - 1) && s_centered;

    if (interior) {
        // ---- fast path: front-batched register window, offsets = s-3 ----
        float2 win[WIN];
        const float* base = y + (size_t)(i0 - 3) * (size_t)B + col;
        #pragma unroll
        for (int k = 0; k < WIN; ++k)
            win[k] = *reinterpret_cast<const float2*>(base + (size_t)k * (size_t)B);

        float* obase = out + (size_t)i0 * (size_t)B + col;
        #pragma unroll
        for (int r = 0; r < TR; ++r) {
            float2 acc = make_float2(0.f, 0.f);
            #pragma unroll
            for (int s = 0; s < S_W; ++s) {
                const float  w = s_w[r * S_W + s];
                const float2 v = win[r + s];
                acc.x = fmaf(w, v.x, acc.x);
                acc.y = fmaf(w, v.y, acc.y);
            }
            *reinterpret_cast<float2*>(obase + (size_t)r * (size_t)B) = acc;
        }
    } else {
        // ---- generic path: boundary / partial / non-centered tiles ----
        #pragma unroll
        for (int r = 0; r < TR; ++r) {
            const int i = i0 + r;
            if (i >= N) break;
            float2 acc = make_float2(0.f, 0.f);
            #pragma unroll
            for (int s = 0; s < S_W; ++s) {
                const float w = s_w[r * S_W + s];
                const int   j = i + s_o[r * S_W + s];
                const float2 v = *reinterpret_cast<const float2*>(
                    y + (size_t)j * (size_t)B + col);
                acc.x = fmaf(w, v.x, acc.x);
                acc.y = fmaf(w, v.y, acc.y);
            }
            *reinterpret_cast<float2*>(out + (size_t)i * (size_t)B + col) = acc;
        }
    }
}

// Fully generic scalar fallback (any N, B).
__global__ void findiff_scalar_kernel(const float* __restrict__ y,
                                      const float* __restrict__ coef,
                                      const int* __restrict__ offs,
                                      float* __restrict__ out,
                                      int N, int B)
{
    const long long total = (long long)N * B;
    for (long long idx = (long long)blockIdx.x * blockDim.x + threadIdx.x;
         idx < total;
         idx += (long long)gridDim.x * blockDim.x) {
        const int i = (int)(idx / B);
        const int b = (int)(idx % B);
        float acc = 0.f;
        #pragma unroll
        for (int s = 0; s < S_W; ++s) {
            const float w = coef[i * S_W + s];
            const int   j = i + offs[i * S_W + s];
            acc = fmaf(w, y[(size_t)j * (size_t)B + b], acc);
        }
        out[idx] = acc;
    }
}

extern "C" void kernel_launch(void* const* d_in, const int* in_sizes, int n_in,
                              void* d_out, int out_size)
{
    const float* y    = (const float*)d_in[0];
    const float* coef = (const float*)d_in[1];
    const int*   offs = (const int*)d_in[2];
    float* out = (float*)d_out;

    const int N = in_sizes[1] / S_W;       // all_coefficients is [N, 7]
    const int B = in_sizes[0] / N;         // y is [N, B]

    if ((B % COLS_PER_BLOCK) == 0) {
        dim3 grid((N + TR - 1) / TR, B / COLS_PER_BLOCK);
        findiff_r15_kernel<<<grid, TPB>>>(y, coef, offs, out, N, B);
    } else {
        const long long total = (long long)N * B;
        int blocks = (int)((total + 255) / 256);
        if (blocks > 65535 * 32) blocks = 65535 * 32;
        findiff_scalar_kernel<<<blocks, 256>>>(y, coef, offs, out, N, B);
    }
}